// round 12
// baseline (speedup 1.0000x reference)
#include <cuda_runtime.h>
#include <cstdint>

// GatingFeatureExtractor: p[B, E=8, C=1000] fp32 -> feats[B, E*C + 3E + 5] fp32.
// Split-row, single kernel: 2 CTAs per row (128 threads, ~16KB smem each) so
// ~12 independent CTAs/SM pipeline load/compute/store via the HW scheduler.
// CTA x -> (b = x>>1, half = x&1), classes [500*half, +500):
//   A: cp.async 16KB stage    B: warp w -> experts 2w,2w+1 top2/argmax -> smem
//   C: thread t<125 owns 4 classes: plogp[8], prefix-KL cross, mixture
//      entropy, variance partials     D: shifted aligned copy of 8 segments
//   E: thread 0 posts 36 partial scalars to __device__ scratch, threadfence,
//      atomic ticket; second CTA of the row merges both halves and writes the
//      29 stat columns, then resets the ticket (graph-replay safe).

#define EPS_F 1e-8f

constexpr int E = 8;
constexpr int C = 1000;
constexpr int EC = E * C;                  // 8000
constexpr int OUTW = EC + 3 * E + 5;       // 8029
constexpr int HALF = 500;                  // classes per CTA
constexpr int H4 = HALF / 4;               // 125 float4 per expert-segment
constexpr int NT = 128;
constexpr int NW = NT / 32;                // 4
constexpr int BMAX = 8192;

// partial scratch: index x = 2*b + half
__device__ float g_red[2 * BMAX][11];      // [0..7]=plogp, 8=cross, 9=mixent, 10=var
__device__ float g_m1[2 * BMAX][E];
__device__ float g_m2[2 * BMAX][E];
__device__ int   g_i1[2 * BMAX][E];
__device__ int   g_cnt[BMAX];              // zero-init; reset after merge

__device__ __forceinline__ void cp_async16(uint32_t saddr, const void* gptr) {
    asm volatile("cp.async.cg.shared.global [%0], [%1], 16;\n" ::"r"(saddr), "l"(gptr));
}

__global__ __launch_bounds__(NT)
void gating_feats_k1(const float* __restrict__ pin, float* __restrict__ out)
{
    __shared__ __align__(16) float sp[E * HALF];   // 16000 B
    __shared__ float sh_red[NW][11];
    __shared__ float sh_m1[E], sh_m2[E];
    __shared__ int   sh_i1[E];

    const int x    = blockIdx.x;
    const int b    = x >> 1;
    const int half = x & 1;
    const int tid  = threadIdx.x;
    const int wid  = tid >> 5;
    const int lane = tid & 31;

    const float* __restrict__ pr = pin + (size_t)b * EC + half * HALF; // + e*C
    float* __restrict__ orow = out + (size_t)b * OUTW;
    // (b*OUTW)%4 == b%4 since OUTW%4==1; every segment start has same h.
    const int h = (4 - (b & 3)) & 3;

    // ---------------- Phase A: stage 8 x 2000B segments via cp.async ----------
    if (tid < H4) {
        uint32_t sbase = (uint32_t)__cvta_generic_to_shared(sp) + 16u * (uint32_t)tid;
#pragma unroll
        for (int e = 0; e < E; e++)
            cp_async16(sbase + (uint32_t)(e * HALF * 4), pr + e * C + 4 * tid);
    }
    asm volatile("cp.async.commit_group;\n" ::: "memory");
    asm volatile("cp.async.wait_group 0;\n" ::: "memory");
    __syncthreads();

    // -------- Phase B: warp w -> experts 2w, 2w+1: top2/argmax partial --------
#pragma unroll
    for (int s = 0; s < 2; s++) {
        const int e = 2 * wid + s;
        const float4* __restrict__ row4 = reinterpret_cast<const float4*>(sp + e * HALF);
        float m1 = -1.f, m2 = -1.f;
        int i1 = 0x7fffffff;
#pragma unroll
        for (int k = 0; k < 4; k++) {
            int idx = lane + 32 * k;
            if (idx < H4) {
                float4 v = row4[idx];
                float vv[4] = {v.x, v.y, v.z, v.w};
#pragma unroll
                for (int i = 0; i < 4; i++) {
                    float f = vv[i];
                    if (f > m1) { m2 = m1; m1 = f; i1 = half * HALF + 4 * idx + i; }
                    else        { m2 = fmaxf(m2, f); }
                }
            }
        }
#pragma unroll
        for (int off = 16; off; off >>= 1) {
            float o1 = __shfl_xor_sync(0xffffffffu, m1, off);
            float o2 = __shfl_xor_sync(0xffffffffu, m2, off);
            int   oi = __shfl_xor_sync(0xffffffffu, i1, off);
            if (o1 > m1 || (o1 == m1 && oi < i1)) {
                m2 = fmaxf(m1, o2); m1 = o1; i1 = oi;
            } else {
                m2 = fmaxf(m2, o1);
            }
        }
        if (lane == 0) { sh_m1[e] = m1; sh_m2[e] = m2; sh_i1[e] = i1; }
    }

    // -------- Phase C: thread t<125 owns local classes 4t..4t+3 --------
    {
        float plogp[E];
#pragma unroll
        for (int e = 0; e < E; e++) plogp[e] = 0.f;
        float s_cross = 0.f, s_mixent = 0.f, s_var = 0.f;

        if (tid < H4) {
            float pre[4] = {0.f, 0.f, 0.f, 0.f};
            float ssq[4] = {0.f, 0.f, 0.f, 0.f};
#pragma unroll
            for (int e = 0; e < E; e++) {
                float4 v = reinterpret_cast<const float4*>(sp + e * HALF)[tid];
                float vv[4] = {v.x, v.y, v.z, v.w};
                float pe = 0.f;
#pragma unroll
                for (int i = 0; i < 4; i++) {
                    float f = vv[i];
                    float lg = __logf(f + EPS_F);
                    pe = fmaf(f, lg, pe);
                    s_cross = fmaf(lg, pre[i], s_cross);  // sum_{i<j} p_i * logp_j
                    pre[i] += f;
                    ssq[i] = fmaf(f, f, ssq[i]);
                }
                plogp[e] = pe;
            }
#pragma unroll
            for (int i = 0; i < 4; i++) {
                float m = pre[i] * (1.0f / E);      // full expert sum for this class
                s_mixent = fmaf(-m, __logf(m + EPS_F), s_mixent);
                s_var = fmaf(ssq[i] - (float)E * m * m, 1.0f / (float)(E - 1), s_var);
            }
        }
        float r[11];
#pragma unroll
        for (int e = 0; e < E; e++) r[e] = plogp[e];
        r[8] = s_cross; r[9] = s_mixent; r[10] = s_var;
#pragma unroll
        for (int off = 16; off; off >>= 1)
#pragma unroll
            for (int k = 0; k < 11; k++)
                r[k] += __shfl_xor_sync(0xffffffffu, r[k], off);
        if (lane == 0)
#pragma unroll
            for (int k = 0; k < 11; k++) sh_red[wid][k] = r[k];
    }
    __syncthreads();                               // sh_red / sh_m* complete

    // -------- Phase D: copy 8 segments, shift-corrected aligned STG.128 --------
    {
#pragma unroll
        for (int e = 0; e < E; e++) {
            const float* __restrict__ seg = sp + e * HALF;
            const float4* __restrict__ seg4 = reinterpret_cast<const float4*>(seg);
            float* __restrict__ dseg = orow + e * C + half * HALF;
            if (h == 0) {
                if (tid < H4)
                    reinterpret_cast<float4*>(dseg)[tid] = seg4[tid];
            } else {
                // 500 = h + 4*124 + (4-h); all reads within this segment
                if (tid < h) dseg[tid] = seg[tid];
                if (tid < 124) {
                    float4 v = seg4[tid];
                    float4 w = seg4[tid + 1];
                    float4 o;
                    if (h == 1)      { o.x = v.y; o.y = v.z; o.z = v.w; o.w = w.x; }
                    else if (h == 2) { o.x = v.z; o.y = v.w; o.z = w.x; o.w = w.y; }
                    else             { o.x = v.w; o.y = w.x; o.z = w.y; o.w = w.z; }
                    *reinterpret_cast<float4*>(dseg + h + 4 * tid) = o;
                }
                if (tid < 4 - h) dseg[h + 496 + tid] = seg[h + 496 + tid];
            }
        }
    }

    // -------- Phase E: post partials, ticket, second CTA merges --------
    if (tid == 0) {
        float acc[11];
#pragma unroll
        for (int k = 0; k < 11; k++) {
            acc[k] = sh_red[0][k] + sh_red[1][k] + sh_red[2][k] + sh_red[3][k];
            g_red[x][k] = acc[k];
        }
#pragma unroll
        for (int e = 0; e < E; e++) {
            g_m1[x][e] = sh_m1[e]; g_m2[x][e] = sh_m2[e]; g_i1[x][e] = sh_i1[e];
        }
        __threadfence();
        int old = atomicAdd(&g_cnt[b], 1);
        if (old == 1) {
            // ---- merge both halves (read back via volatile = L2-coherent) ----
            const int p0 = 2 * b, p1 = 2 * b + 1;
            const volatile float* r0 = g_red[p0];
            const volatile float* r1 = g_red[p1];
            float a[11];
#pragma unroll
            for (int k = 0; k < 11; k++) a[k] = r0[k] + r1[k];

            float sum_pl = 0.f, wsum = 0.f;
            int args[E];
#pragma unroll
            for (int e = 0; e < E; e++) {
                float m1 = ((volatile float*)g_m1[p0])[e];
                float m2 = ((volatile float*)g_m2[p0])[e];
                int   i1 = ((volatile int*)g_i1[p0])[e];
                float o1 = ((volatile float*)g_m1[p1])[e];
                float o2 = ((volatile float*)g_m2[p1])[e];
                int   oi = ((volatile int*)g_i1[p1])[e];
                if (o1 > m1 || (o1 == m1 && oi < i1)) {
                    m2 = fmaxf(m1, o2); m1 = o1; i1 = oi;
                } else {
                    m2 = fmaxf(m2, o1);
                }
                float pl = a[e];
                orow[EC + e]         = -pl;                  // expert_entropy
                orow[EC + E + e]     = m1;                   // expert_confidence
                orow[EC + 2 * E + e] = m1 - m2;              // expert_margin
                sum_pl += pl;
                wsum = fmaf(pl, (float)(E - 1 - e), wsum);
                args[e] = i1;
            }

            // disagreement: sort 8 argmax indices, count unique
            for (int i = 1; i < E; i++) {
                int key = args[i]; int j = i - 1;
                while (j >= 0 && args[j] > key) { args[j + 1] = args[j]; j--; }
                args[j + 1] = key;
            }
            int nuniq = 1;
            for (int i = 1; i < E; i++) nuniq += (args[i] != args[i - 1]) ? 1 : 0;

            const int n_pairs = E * (E - 1) / 2;
            orow[EC + 3 * E + 0] = (float)(nuniq - 1) / (float)(E - 1);
            orow[EC + 3 * E + 1] = (wsum - a[8]) / (float)n_pairs;
            orow[EC + 3 * E + 2] = a[9];
            orow[EC + 3 * E + 3] = a[10] / (float)C;
            orow[EC + 3 * E + 4] = a[9] + sum_pl / (float)E;

            g_cnt[b] = 0;                          // reset: graph-replay safe
        }
    }
}

extern "C" void kernel_launch(void* const* d_in, const int* in_sizes, int n_in,
                              void* d_out, int out_size)
{
    const float* p = (const float*)d_in[0];
    float* out = (float*)d_out;
    const int B = in_sizes[0] / EC;    // 8192 for this problem's shapes
    gating_feats_k1<<<2 * B, NT>>>(p, out);
}

// round 13
// speedup vs baseline: 1.1597x; 1.1597x over previous
#include <cuda_runtime.h>
#include <cstdint>

// GatingFeatureExtractor: p[B, E=8, C=1000] fp32 -> feats[B, E*C + 3E + 5] fp32.
// Split-row design (R11): 2 CTAs per row (128 threads, ~16KB smem each) so
// ~12 independent CTAs/SM pipeline load/compute/store via the HW scheduler.
//   k1 (grid 2B): CTA x -> (b = x>>1, half = x&1), classes [500*half, +500):
//     A: cp.async 16KB stage   B: warp w -> experts 2w,2w+1 top2/argmax partial
//     C: thread t<125 owns 4 classes: plogp[8], prefix-KL cross, mixture
//        entropy, variance partials    D: shifted aligned copy of 8 segments
//     partials -> __device__ scratch (SoA layout for coalesced k2 reads)
//   k2 (1 thread/row): merge 2 partials (coalesced SoA loads), write 29 cols.

#define EPS_F 1e-8f

constexpr int E = 8;
constexpr int C = 1000;
constexpr int EC = E * C;                  // 8000
constexpr int OUTW = EC + 3 * E + 5;       // 8029
constexpr int HALF = 500;                  // classes per CTA
constexpr int H4 = HALF / 4;               // 125 float4 per expert-segment
constexpr int NT = 128;
constexpr int NW = NT / 32;                // 4
constexpr int BMAX = 8192;

// partial scratch, SoA: index x = 2*b + half (adjacent halves adjacent in mem)
__device__ float g_red[11][2 * BMAX];      // [0..7]=plogp, 8=cross, 9=mixent, 10=var
__device__ float g_m1[E][2 * BMAX];
__device__ float g_m2[E][2 * BMAX];
__device__ int   g_i1[E][2 * BMAX];

__device__ __forceinline__ void cp_async16(uint32_t saddr, const void* gptr) {
    asm volatile("cp.async.cg.shared.global [%0], [%1], 16;\n" ::"r"(saddr), "l"(gptr));
}

__global__ __launch_bounds__(NT)
void gating_feats_k1(const float* __restrict__ pin, float* __restrict__ out)
{
    __shared__ __align__(16) float sp[E * HALF];   // 16000 B
    __shared__ float sh_red[NW][11];

    const int x    = blockIdx.x;
    const int b    = x >> 1;
    const int half = x & 1;
    const int tid  = threadIdx.x;
    const int wid  = tid >> 5;
    const int lane = tid & 31;

    const float* __restrict__ pr = pin + (size_t)b * EC + half * HALF; // + e*C
    float* __restrict__ orow = out + (size_t)b * OUTW;
    // (b*OUTW)%4 == b%4 since OUTW%4==1; every segment start has same h.
    const int h = (4 - (b & 3)) & 3;

    // ---------------- Phase A: stage 8 x 2000B segments via cp.async ----------
    if (tid < H4) {
        uint32_t sbase = (uint32_t)__cvta_generic_to_shared(sp) + 16u * (uint32_t)tid;
#pragma unroll
        for (int e = 0; e < E; e++)
            cp_async16(sbase + (uint32_t)(e * HALF * 4), pr + e * C + 4 * tid);
    }
    asm volatile("cp.async.commit_group;\n" ::: "memory");
    asm volatile("cp.async.wait_group 0;\n" ::: "memory");
    __syncthreads();

    // -------- Phase B: warp w -> experts 2w, 2w+1: top2/argmax partial --------
#pragma unroll
    for (int s = 0; s < 2; s++) {
        const int e = 2 * wid + s;
        const float4* __restrict__ row4 = reinterpret_cast<const float4*>(sp + e * HALF);
        float m1 = -1.f, m2 = -1.f;
        int i1 = 0x7fffffff;
#pragma unroll
        for (int k = 0; k < 4; k++) {
            int idx = lane + 32 * k;
            if (idx < H4) {
                float4 v = row4[idx];
                float vv[4] = {v.x, v.y, v.z, v.w};
#pragma unroll
                for (int i = 0; i < 4; i++) {
                    float f = vv[i];
                    if (f > m1) { m2 = m1; m1 = f; i1 = half * HALF + 4 * idx + i; }
                    else        { m2 = fmaxf(m2, f); }
                }
            }
        }
#pragma unroll
        for (int off = 16; off; off >>= 1) {
            float o1 = __shfl_xor_sync(0xffffffffu, m1, off);
            float o2 = __shfl_xor_sync(0xffffffffu, m2, off);
            int   oi = __shfl_xor_sync(0xffffffffu, i1, off);
            if (o1 > m1 || (o1 == m1 && oi < i1)) {
                m2 = fmaxf(m1, o2); m1 = o1; i1 = oi;
            } else {
                m2 = fmaxf(m2, o1);
            }
        }
        if (lane == 0) { g_m1[e][x] = m1; g_m2[e][x] = m2; g_i1[e][x] = i1; }
    }

    // -------- Phase C: thread t<125 owns local classes 4t..4t+3 --------
    {
        float plogp[E];
#pragma unroll
        for (int e = 0; e < E; e++) plogp[e] = 0.f;
        float s_cross = 0.f, s_mixent = 0.f, s_var = 0.f;

        if (tid < H4) {
            float pre[4] = {0.f, 0.f, 0.f, 0.f};
            float ssq[4] = {0.f, 0.f, 0.f, 0.f};
#pragma unroll
            for (int e = 0; e < E; e++) {
                float4 v = reinterpret_cast<const float4*>(sp + e * HALF)[tid];
                float vv[4] = {v.x, v.y, v.z, v.w};
                float pe = 0.f;
#pragma unroll
                for (int i = 0; i < 4; i++) {
                    float f = vv[i];
                    float lg = __logf(f + EPS_F);
                    pe = fmaf(f, lg, pe);
                    s_cross = fmaf(lg, pre[i], s_cross);  // sum_{i<j} p_i * logp_j
                    pre[i] += f;
                    ssq[i] = fmaf(f, f, ssq[i]);
                }
                plogp[e] = pe;
            }
#pragma unroll
            for (int i = 0; i < 4; i++) {
                float m = pre[i] * (1.0f / E);      // full expert sum for this class
                s_mixent = fmaf(-m, __logf(m + EPS_F), s_mixent);
                s_var = fmaf(ssq[i] - (float)E * m * m, 1.0f / (float)(E - 1), s_var);
            }
        }
        float r[11];
#pragma unroll
        for (int e = 0; e < E; e++) r[e] = plogp[e];
        r[8] = s_cross; r[9] = s_mixent; r[10] = s_var;
#pragma unroll
        for (int off = 16; off; off >>= 1)
#pragma unroll
            for (int k = 0; k < 11; k++)
                r[k] += __shfl_xor_sync(0xffffffffu, r[k], off);
        if (lane == 0)
#pragma unroll
            for (int k = 0; k < 11; k++) sh_red[wid][k] = r[k];
    }
    __syncthreads();
    if (tid == 0) {
#pragma unroll
        for (int k = 0; k < 11; k++)
            g_red[k][x] = sh_red[0][k] + sh_red[1][k] + sh_red[2][k] + sh_red[3][k];
    }

    // -------- Phase D: copy 8 segments, shift-corrected aligned STG.128 --------
    {
#pragma unroll
        for (int e = 0; e < E; e++) {
            const float* __restrict__ seg = sp + e * HALF;
            const float4* __restrict__ seg4 = reinterpret_cast<const float4*>(seg);
            float* __restrict__ dseg = orow + e * C + half * HALF;   // b%4 offset
            if (h == 0) {
                if (tid < H4)
                    reinterpret_cast<float4*>(dseg)[tid] = seg4[tid];
            } else {
                // 500 = h + 4*124 + (4-h); all reads within this segment
                if (tid < h) dseg[tid] = seg[tid];
                if (tid < 124) {
                    float4 v = seg4[tid];
                    float4 w = seg4[tid + 1];
                    float4 o;
                    if (h == 1)      { o.x = v.y; o.y = v.z; o.z = v.w; o.w = w.x; }
                    else if (h == 2) { o.x = v.z; o.y = v.w; o.z = w.x; o.w = w.y; }
                    else             { o.x = v.w; o.y = w.x; o.z = w.y; o.w = w.z; }
                    *reinterpret_cast<float4*>(dseg + h + 4 * tid) = o;
                }
                if (tid < 4 - h) dseg[h + 496 + tid] = seg[h + 496 + tid];
            }
        }
    }
}

// ---- combine: 1 thread per row merges the two halves (coalesced SoA loads) ----
__global__ void gating_feats_k2(float* __restrict__ out, int B)
{
    int b = blockIdx.x * blockDim.x + threadIdx.x;
    if (b >= B) return;
    float* __restrict__ orow = out + (size_t)b * OUTW;
    const int p0 = 2 * b, p1 = 2 * b + 1;

    float acc[11];
#pragma unroll
    for (int k = 0; k < 11; k++) acc[k] = g_red[k][p0] + g_red[k][p1];

    float sum_pl = 0.f, wsum = 0.f;
    int args[E];
#pragma unroll
    for (int e = 0; e < E; e++) {
        float m1 = g_m1[e][p0], m2 = g_m2[e][p0];
        int   i1 = g_i1[e][p0];
        float o1 = g_m1[e][p1], o2 = g_m2[e][p1];
        int   oi = g_i1[e][p1];
        if (o1 > m1 || (o1 == m1 && oi < i1)) {
            m2 = fmaxf(m1, o2); m1 = o1; i1 = oi;
        } else {
            m2 = fmaxf(m2, o1);
        }
        float pl = acc[e];
        orow[EC + e]         = -pl;                  // expert_entropy
        orow[EC + E + e]     = m1;                   // expert_confidence
        orow[EC + 2 * E + e] = m1 - m2;              // expert_margin
        sum_pl += pl;
        wsum = fmaf(pl, (float)(E - 1 - e), wsum);
        args[e] = i1;
    }

    // disagreement: sort 8 argmax indices, count unique
    for (int i = 1; i < E; i++) {
        int key = args[i]; int j = i - 1;
        while (j >= 0 && args[j] > key) { args[j + 1] = args[j]; j--; }
        args[j + 1] = key;
    }
    int nuniq = 1;
    for (int i = 1; i < E; i++) nuniq += (args[i] != args[i - 1]) ? 1 : 0;

    const int n_pairs = E * (E - 1) / 2;
    orow[EC + 3 * E + 0] = (float)(nuniq - 1) / (float)(E - 1);  // disagreement_ratio
    orow[EC + 3 * E + 1] = (wsum - acc[8]) / (float)n_pairs;     // mean_pairwise_kl
    orow[EC + 3 * E + 2] = acc[9];                               // mixture_entropy
    orow[EC + 3 * E + 3] = acc[10] / (float)C;                   // post_var
    orow[EC + 3 * E + 4] = acc[9] + sum_pl / (float)E;           // mutual_info
}

extern "C" void kernel_launch(void* const* d_in, const int* in_sizes, int n_in,
                              void* d_out, int out_size)
{
    const float* p = (const float*)d_in[0];
    float* out = (float*)d_out;
    const int B = in_sizes[0] / EC;    // 8192 for this problem's shapes
    gating_feats_k1<<<2 * B, NT>>>(p, out);
    gating_feats_k2<<<(B + 127) / 128, 128>>>(out, B);
}

// round 14
// speedup vs baseline: 1.2035x; 1.0378x over previous
#include <cuda_runtime.h>
#include <cstdint>

// GatingFeatureExtractor: p[B, E=8, C=1000] fp32 -> feats[B, E*C + 3E + 5] fp32.
// Split-row design: 2 CTAs per row (128 threads, ~16KB smem each) so ~10-12
// independent CTAs/SM pipeline load/compute/store via the HW scheduler.
//   k1 (grid 2B): CTA x -> (b = x>>1, half = x&1), classes [500*half, +500):
//     A: cp.async 16KB stage   B: warp w -> experts 2w,2w+1 top2/argmax partial
//     C: thread t<125 owns 4 classes: plogp[8], prefix-KL cross, mixture
//        entropy, variance partials    D: shifted aligned copy of 8 segments
//     partials -> __device__ scratch (SoA, halves adjacent -> float2 in k2)
//   k2 (thread per (row, expert), 8x parallel): merge halves via float2 loads,
//     write 3 per-expert cols; 8-lane shuffle reduce -> lane e==0 writes the 5
//     per-row scalars.

#define EPS_F 1e-8f

constexpr int E = 8;
constexpr int C = 1000;
constexpr int EC = E * C;                  // 8000
constexpr int OUTW = EC + 3 * E + 5;       // 8029
constexpr int HALF = 500;                  // classes per CTA
constexpr int H4 = HALF / 4;               // 125 float4 per expert-segment
constexpr int NT = 128;
constexpr int NW = NT / 32;                // 4
constexpr int BMAX = 8192;

// partial scratch, SoA: index x = 2*b + half (halves adjacent -> float2 loads)
__device__ float g_red[11][2 * BMAX];      // [0..7]=plogp, 8=cross, 9=mixent, 10=var
__device__ float g_m1[E][2 * BMAX];
__device__ float g_m2[E][2 * BMAX];
__device__ int   g_i1[E][2 * BMAX];

__device__ __forceinline__ void cp_async16(uint32_t saddr, const void* gptr) {
    asm volatile("cp.async.cg.shared.global [%0], [%1], 16;\n" ::"r"(saddr), "l"(gptr));
}

__global__ __launch_bounds__(NT)
void gating_feats_k1(const float* __restrict__ pin, float* __restrict__ out)
{
    __shared__ __align__(16) float sp[E * HALF];   // 16000 B
    __shared__ float sh_red[NW][11];

    const int x    = blockIdx.x;
    const int b    = x >> 1;
    const int half = x & 1;
    const int tid  = threadIdx.x;
    const int wid  = tid >> 5;
    const int lane = tid & 31;

    const float* __restrict__ pr = pin + (size_t)b * EC + half * HALF; // + e*C
    float* __restrict__ orow = out + (size_t)b * OUTW;
    // (b*OUTW)%4 == b%4 since OUTW%4==1; every segment start has same h.
    const int h = (4 - (b & 3)) & 3;

    // ---------------- Phase A: stage 8 x 2000B segments via cp.async ----------
    if (tid < H4) {
        uint32_t sbase = (uint32_t)__cvta_generic_to_shared(sp) + 16u * (uint32_t)tid;
#pragma unroll
        for (int e = 0; e < E; e++)
            cp_async16(sbase + (uint32_t)(e * HALF * 4), pr + e * C + 4 * tid);
    }
    asm volatile("cp.async.commit_group;\n" ::: "memory");
    asm volatile("cp.async.wait_group 0;\n" ::: "memory");
    __syncthreads();

    // -------- Phase B: warp w -> experts 2w, 2w+1: top2/argmax partial --------
#pragma unroll
    for (int s = 0; s < 2; s++) {
        const int e = 2 * wid + s;
        const float4* __restrict__ row4 = reinterpret_cast<const float4*>(sp + e * HALF);
        float m1 = -1.f, m2 = -1.f;
        int i1 = 0x7fffffff;
#pragma unroll
        for (int k = 0; k < 4; k++) {
            int idx = lane + 32 * k;
            if (idx < H4) {
                float4 v = row4[idx];
                float vv[4] = {v.x, v.y, v.z, v.w};
#pragma unroll
                for (int i = 0; i < 4; i++) {
                    float f = vv[i];
                    if (f > m1) { m2 = m1; m1 = f; i1 = half * HALF + 4 * idx + i; }
                    else        { m2 = fmaxf(m2, f); }
                }
            }
        }
#pragma unroll
        for (int off = 16; off; off >>= 1) {
            float o1 = __shfl_xor_sync(0xffffffffu, m1, off);
            float o2 = __shfl_xor_sync(0xffffffffu, m2, off);
            int   oi = __shfl_xor_sync(0xffffffffu, i1, off);
            if (o1 > m1 || (o1 == m1 && oi < i1)) {
                m2 = fmaxf(m1, o2); m1 = o1; i1 = oi;
            } else {
                m2 = fmaxf(m2, o1);
            }
        }
        if (lane == 0) { g_m1[e][x] = m1; g_m2[e][x] = m2; g_i1[e][x] = i1; }
    }

    // -------- Phase C: thread t<125 owns local classes 4t..4t+3 --------
    {
        float plogp[E];
#pragma unroll
        for (int e = 0; e < E; e++) plogp[e] = 0.f;
        float s_cross = 0.f, s_mixent = 0.f, s_var = 0.f;

        if (tid < H4) {
            float pre[4] = {0.f, 0.f, 0.f, 0.f};
            float ssq[4] = {0.f, 0.f, 0.f, 0.f};
#pragma unroll
            for (int e = 0; e < E; e++) {
                float4 v = reinterpret_cast<const float4*>(sp + e * HALF)[tid];
                float vv[4] = {v.x, v.y, v.z, v.w};
                float pe = 0.f;
#pragma unroll
                for (int i = 0; i < 4; i++) {
                    float f = vv[i];
                    float lg = __logf(f + EPS_F);
                    pe = fmaf(f, lg, pe);
                    s_cross = fmaf(lg, pre[i], s_cross);  // sum_{i<j} p_i * logp_j
                    pre[i] += f;
                    ssq[i] = fmaf(f, f, ssq[i]);
                }
                plogp[e] = pe;
            }
#pragma unroll
            for (int i = 0; i < 4; i++) {
                float m = pre[i] * (1.0f / E);      // full expert sum for this class
                s_mixent = fmaf(-m, __logf(m + EPS_F), s_mixent);
                s_var = fmaf(ssq[i] - (float)E * m * m, 1.0f / (float)(E - 1), s_var);
            }
        }
        float r[11];
#pragma unroll
        for (int e = 0; e < E; e++) r[e] = plogp[e];
        r[8] = s_cross; r[9] = s_mixent; r[10] = s_var;
#pragma unroll
        for (int off = 16; off; off >>= 1)
#pragma unroll
            for (int k = 0; k < 11; k++)
                r[k] += __shfl_xor_sync(0xffffffffu, r[k], off);
        if (lane == 0)
#pragma unroll
            for (int k = 0; k < 11; k++) sh_red[wid][k] = r[k];
    }
    __syncthreads();
    if (tid == 0) {
#pragma unroll
        for (int k = 0; k < 11; k++)
            g_red[k][x] = sh_red[0][k] + sh_red[1][k] + sh_red[2][k] + sh_red[3][k];
    }

    // -------- Phase D: copy 8 segments, shift-corrected aligned STG.128 --------
    {
#pragma unroll
        for (int e = 0; e < E; e++) {
            const float* __restrict__ seg = sp + e * HALF;
            const float4* __restrict__ seg4 = reinterpret_cast<const float4*>(seg);
            float* __restrict__ dseg = orow + e * C + half * HALF;   // b%4 offset
            if (h == 0) {
                if (tid < H4)
                    reinterpret_cast<float4*>(dseg)[tid] = seg4[tid];
            } else {
                // 500 = h + 4*124 + (4-h); all reads within this segment
                if (tid < h) dseg[tid] = seg[tid];
                if (tid < 124) {
                    float4 v = seg4[tid];
                    float4 w = seg4[tid + 1];
                    float4 o;
                    if (h == 1)      { o.x = v.y; o.y = v.z; o.z = v.w; o.w = w.x; }
                    else if (h == 2) { o.x = v.z; o.y = v.w; o.z = w.x; o.w = w.y; }
                    else             { o.x = v.w; o.y = w.x; o.z = w.y; o.w = w.z; }
                    *reinterpret_cast<float4*>(dseg + h + 4 * tid) = o;
                }
                if (tid < 4 - h) dseg[h + 496 + tid] = seg[h + 496 + tid];
            }
        }
    }
}

// ---- combine: thread (b, e) merges expert e of row b; lane e==0 of each
//      8-lane group writes the 5 per-row scalars. ----
__global__ __launch_bounds__(256)
void gating_feats_k2(float* __restrict__ out, int B)
{
    const int g = blockIdx.x * blockDim.x + threadIdx.x;   // B*8 threads
    const int b = g >> 3;
    const int e = g & 7;
    if (b >= B) return;
    float* __restrict__ orow = out + (size_t)b * OUTW;

    // two halves of expert e, adjacent in SoA scratch -> one float2 each
    const float2 m1p = reinterpret_cast<const float2*>(g_m1[e])[b];
    const float2 m2p = reinterpret_cast<const float2*>(g_m2[e])[b];
    const int2   i1p = reinterpret_cast<const int2*>(g_i1[e])[b];
    const float2 plp = reinterpret_cast<const float2*>(g_red[e])[b];

    float m1 = m1p.x, m2 = m2p.x;
    int   i1 = i1p.x;
    {
        float o1 = m1p.y, o2 = m2p.y;
        int   oi = i1p.y;
        if (o1 > m1 || (o1 == m1 && oi < i1)) {
            m2 = fmaxf(m1, o2); m1 = o1; i1 = oi;
        } else {
            m2 = fmaxf(m2, o1);
        }
    }
    const float pl = plp.x + plp.y;

    orow[EC + e]         = -pl;          // expert_entropy
    orow[EC + E + e]     = m1;           // expert_confidence
    orow[EC + 2 * E + e] = m1 - m2;      // expert_margin

    // 8-lane group reductions (groups are lane-aligned: blockDim % 8 == 0)
    float spl = pl, wsum = pl * (float)(E - 1 - e);
#pragma unroll
    for (int off = 4; off; off >>= 1) {
        spl  += __shfl_xor_sync(0xffffffffu, spl, off);
        wsum += __shfl_xor_sync(0xffffffffu, wsum, off);
    }
    // gather the 8 argmax indices of this row to every lane (use e==0's copy)
    const int lane = threadIdx.x & 31;
    const int base = lane & ~7;
    int args[E];
#pragma unroll
    for (int j = 0; j < E; j++)
        args[j] = __shfl_sync(0xffffffffu, i1, base + j);

    if (e == 0) {
        // sort 8 argmax indices, count unique
        for (int i = 1; i < E; i++) {
            int key = args[i]; int j = i - 1;
            while (j >= 0 && args[j] > key) { args[j + 1] = args[j]; j--; }
            args[j + 1] = key;
        }
        int nuniq = 1;
        for (int i = 1; i < E; i++) nuniq += (args[i] != args[i - 1]) ? 1 : 0;

        const float2 cr = reinterpret_cast<const float2*>(g_red[8])[b];
        const float2 me = reinterpret_cast<const float2*>(g_red[9])[b];
        const float2 va = reinterpret_cast<const float2*>(g_red[10])[b];
        const float Sx = cr.x + cr.y;
        const float mixent = me.x + me.y;
        const float varsum = va.x + va.y;
        const int n_pairs = E * (E - 1) / 2;

        orow[EC + 3 * E + 0] = (float)(nuniq - 1) / (float)(E - 1);  // disagreement
        orow[EC + 3 * E + 1] = (wsum - Sx) / (float)n_pairs;         // mean_pairwise_kl
        orow[EC + 3 * E + 2] = mixent;                               // mixture_entropy
        orow[EC + 3 * E + 3] = varsum / (float)C;                    // post_var
        orow[EC + 3 * E + 4] = mixent + spl / (float)E;              // mutual_info
    }
}

extern "C" void kernel_launch(void* const* d_in, const int* in_sizes, int n_in,
                              void* d_out, int out_size)
{
    const float* p = (const float*)d_in[0];
    float* out = (float*)d_out;
    const int B = in_sizes[0] / EC;    // 8192 for this problem's shapes
    gating_feats_k1<<<2 * B, NT>>>(p, out);
    gating_feats_k2<<<(B * E + 255) / 256, 256>>>(out, B);
}

// round 15
// speedup vs baseline: 1.2060x; 1.0021x over previous
#include <cuda_runtime.h>
#include <cstdint>

// GatingFeatureExtractor: p[B, E=8, C=1000] fp32 -> feats[B, E*C + 3E + 5] fp32.
// Split-row design: 2 CTAs per row (128 threads, ~16KB smem each) so ~10-12
// independent CTAs/SM pipeline load/compute/store via the HW scheduler.
//   k1 (grid 2B): CTA x -> (b = x>>1, half = x&1), classes [500*half, +500):
//     A: cp.async 16KB stage   B: warp w -> experts 2w,2w+1 top2/argmax partial
//     C: thread t<125 owns 4 classes: plogp[8], prefix-KL cross, mixture
//        entropy, variance partials    D: shifted aligned copy of 8 segments
//     partials -> __device__ scratch (AoS-by-x: 8-lane-coalesced k2 reads)
//   k2 (thread per (row, expert)): merge halves, write 3 per-expert cols;
//     8-lane shuffle reduce -> lane e==0 writes the 5 per-row scalars.

#define EPS_F 1e-8f

constexpr int E = 8;
constexpr int C = 1000;
constexpr int EC = E * C;                  // 8000
constexpr int OUTW = EC + 3 * E + 5;       // 8029
constexpr int HALF = 500;                  // classes per CTA
constexpr int H4 = HALF / 4;               // 125 float4 per expert-segment
constexpr int NT = 128;
constexpr int NW = NT / 32;                // 4
constexpr int BMAX = 8192;

// partial scratch, AoS by x = 2*b + half: lanes e=0..7 read consecutive floats
__device__ float g_red[2 * BMAX][16];      // [0..7]=plogp, 8=cross, 9=mixent, 10=var
__device__ float g_m1[2 * BMAX][E];
__device__ float g_m2[2 * BMAX][E];
__device__ int   g_i1[2 * BMAX][E];

__device__ __forceinline__ void cp_async16(uint32_t saddr, const void* gptr) {
    asm volatile("cp.async.cg.shared.global [%0], [%1], 16;\n" ::"r"(saddr), "l"(gptr));
}

__global__ __launch_bounds__(NT)
void gating_feats_k1(const float* __restrict__ pin, float* __restrict__ out)
{
    __shared__ __align__(16) float sp[E * HALF];   // 16000 B
    __shared__ float sh_red[NW][11];

    const int x    = blockIdx.x;
    const int b    = x >> 1;
    const int half = x & 1;
    const int tid  = threadIdx.x;
    const int wid  = tid >> 5;
    const int lane = tid & 31;

    const float* __restrict__ pr = pin + (size_t)b * EC + half * HALF; // + e*C
    float* __restrict__ orow = out + (size_t)b * OUTW;
    // (b*OUTW)%4 == b%4 since OUTW%4==1; every segment start has same h.
    const int h = (4 - (b & 3)) & 3;

    // ---------------- Phase A: stage 8 x 2000B segments via cp.async ----------
    if (tid < H4) {
        uint32_t sbase = (uint32_t)__cvta_generic_to_shared(sp) + 16u * (uint32_t)tid;
#pragma unroll
        for (int e = 0; e < E; e++)
            cp_async16(sbase + (uint32_t)(e * HALF * 4), pr + e * C + 4 * tid);
    }
    asm volatile("cp.async.commit_group;\n" ::: "memory");
    asm volatile("cp.async.wait_group 0;\n" ::: "memory");
    __syncthreads();

    // -------- Phase B: warp w -> experts 2w, 2w+1: top2/argmax partial --------
#pragma unroll
    for (int s = 0; s < 2; s++) {
        const int e = 2 * wid + s;
        const float4* __restrict__ row4 = reinterpret_cast<const float4*>(sp + e * HALF);
        float m1 = -1.f, m2 = -1.f;
        int i1 = 0x7fffffff;
#pragma unroll
        for (int k = 0; k < 4; k++) {
            int idx = lane + 32 * k;
            if (idx < H4) {
                float4 v = row4[idx];
                float vv[4] = {v.x, v.y, v.z, v.w};
#pragma unroll
                for (int i = 0; i < 4; i++) {
                    float f = vv[i];
                    if (f > m1) { m2 = m1; m1 = f; i1 = half * HALF + 4 * idx + i; }
                    else        { m2 = fmaxf(m2, f); }
                }
            }
        }
#pragma unroll
        for (int off = 16; off; off >>= 1) {
            float o1 = __shfl_xor_sync(0xffffffffu, m1, off);
            float o2 = __shfl_xor_sync(0xffffffffu, m2, off);
            int   oi = __shfl_xor_sync(0xffffffffu, i1, off);
            if (o1 > m1 || (o1 == m1 && oi < i1)) {
                m2 = fmaxf(m1, o2); m1 = o1; i1 = oi;
            } else {
                m2 = fmaxf(m2, o1);
            }
        }
        if (lane == 0) { g_m1[x][e] = m1; g_m2[x][e] = m2; g_i1[x][e] = i1; }
    }

    // -------- Phase C: thread t<125 owns local classes 4t..4t+3 --------
    {
        float plogp[E];
#pragma unroll
        for (int e = 0; e < E; e++) plogp[e] = 0.f;
        float s_cross = 0.f, s_mixent = 0.f, s_var = 0.f;

        if (tid < H4) {
            float pre[4] = {0.f, 0.f, 0.f, 0.f};
            float ssq[4] = {0.f, 0.f, 0.f, 0.f};
#pragma unroll
            for (int e = 0; e < E; e++) {
                float4 v = reinterpret_cast<const float4*>(sp + e * HALF)[tid];
                float vv[4] = {v.x, v.y, v.z, v.w};
                float pe = 0.f;
#pragma unroll
                for (int i = 0; i < 4; i++) {
                    float f = vv[i];
                    float lg = __logf(f + EPS_F);
                    pe = fmaf(f, lg, pe);
                    s_cross = fmaf(lg, pre[i], s_cross);  // sum_{i<j} p_i * logp_j
                    pre[i] += f;
                    ssq[i] = fmaf(f, f, ssq[i]);
                }
                plogp[e] = pe;
            }
#pragma unroll
            for (int i = 0; i < 4; i++) {
                float m = pre[i] * (1.0f / E);      // full expert sum for this class
                s_mixent = fmaf(-m, __logf(m + EPS_F), s_mixent);
                s_var = fmaf(ssq[i] - (float)E * m * m, 1.0f / (float)(E - 1), s_var);
            }
        }
        float r[11];
#pragma unroll
        for (int e = 0; e < E; e++) r[e] = plogp[e];
        r[8] = s_cross; r[9] = s_mixent; r[10] = s_var;
#pragma unroll
        for (int off = 16; off; off >>= 1)
#pragma unroll
            for (int k = 0; k < 11; k++)
                r[k] += __shfl_xor_sync(0xffffffffu, r[k], off);
        if (lane == 0)
#pragma unroll
            for (int k = 0; k < 11; k++) sh_red[wid][k] = r[k];
    }
    __syncthreads();
    if (tid == 0) {
#pragma unroll
        for (int k = 0; k < 11; k++)
            g_red[x][k] = sh_red[0][k] + sh_red[1][k] + sh_red[2][k] + sh_red[3][k];
    }

    // -------- Phase D: copy 8 segments, shift-corrected aligned STG.128 --------
    {
#pragma unroll
        for (int e = 0; e < E; e++) {
            const float* __restrict__ seg = sp + e * HALF;
            const float4* __restrict__ seg4 = reinterpret_cast<const float4*>(seg);
            float* __restrict__ dseg = orow + e * C + half * HALF;   // b%4 offset
            if (h == 0) {
                if (tid < H4)
                    reinterpret_cast<float4*>(dseg)[tid] = seg4[tid];
            } else {
                // 500 = h + 4*124 + (4-h); all reads within this segment
                if (tid < h) dseg[tid] = seg[tid];
                if (tid < 124) {
                    float4 v = seg4[tid];
                    float4 w = seg4[tid + 1];
                    float4 o;
                    if (h == 1)      { o.x = v.y; o.y = v.z; o.z = v.w; o.w = w.x; }
                    else if (h == 2) { o.x = v.z; o.y = v.w; o.z = w.x; o.w = w.y; }
                    else             { o.x = v.w; o.y = w.x; o.z = w.y; o.w = w.z; }
                    *reinterpret_cast<float4*>(dseg + h + 4 * tid) = o;
                }
                if (tid < 4 - h) dseg[h + 496 + tid] = seg[h + 496 + tid];
            }
        }
    }
}

// ---- combine: thread (b, e) merges expert e of row b (coalesced AoS reads);
//      lane e==0 of each 8-lane group writes the 5 per-row scalars. ----
__global__ __launch_bounds__(256)
void gating_feats_k2(float* __restrict__ out, int B)
{
    const int g = blockIdx.x * blockDim.x + threadIdx.x;   // B*8 threads
    const int b = g >> 3;
    const int e = g & 7;
    if (b >= B) return;
    float* __restrict__ orow = out + (size_t)b * OUTW;
    const int p0 = 2 * b, p1 = 2 * b + 1;

    // 8-lane groups read consecutive floats -> one 32B sector per load
    float m1 = g_m1[p0][e], m2 = g_m2[p0][e];
    int   i1 = g_i1[p0][e];
    {
        float o1 = g_m1[p1][e], o2 = g_m2[p1][e];
        int   oi = g_i1[p1][e];
        if (o1 > m1 || (o1 == m1 && oi < i1)) {
            m2 = fmaxf(m1, o2); m1 = o1; i1 = oi;
        } else {
            m2 = fmaxf(m2, o1);
        }
    }
    const float pl = g_red[p0][e] + g_red[p1][e];

    orow[EC + e]         = -pl;          // expert_entropy
    orow[EC + E + e]     = m1;           // expert_confidence
    orow[EC + 2 * E + e] = m1 - m2;      // expert_margin

    // 8-lane group reductions (groups are lane-aligned: blockDim % 8 == 0)
    float spl = pl, wsum = pl * (float)(E - 1 - e);
#pragma unroll
    for (int off = 4; off; off >>= 1) {
        spl  += __shfl_xor_sync(0xffffffffu, spl, off);
        wsum += __shfl_xor_sync(0xffffffffu, wsum, off);
    }
    // gather the 8 argmax indices of this row to every lane
    const int lane = threadIdx.x & 31;
    const int base = lane & ~7;
    int args[E];
#pragma unroll
    for (int j = 0; j < E; j++)
        args[j] = __shfl_sync(0xffffffffu, i1, base + j);

    if (e == 0) {
        // sort 8 argmax indices, count unique
        for (int i = 1; i < E; i++) {
            int key = args[i]; int j = i - 1;
            while (j >= 0 && args[j] > key) { args[j + 1] = args[j]; j--; }
            args[j + 1] = key;
        }
        int nuniq = 1;
        for (int i = 1; i < E; i++) nuniq += (args[i] != args[i - 1]) ? 1 : 0;

        const float Sx     = g_red[p0][8]  + g_red[p1][8];
        const float mixent = g_red[p0][9]  + g_red[p1][9];
        const float varsum = g_red[p0][10] + g_red[p1][10];
        const int n_pairs = E * (E - 1) / 2;

        orow[EC + 3 * E + 0] = (float)(nuniq - 1) / (float)(E - 1);  // disagreement
        orow[EC + 3 * E + 1] = (wsum - Sx) / (float)n_pairs;         // mean_pairwise_kl
        orow[EC + 3 * E + 2] = mixent;                               // mixture_entropy
        orow[EC + 3 * E + 3] = varsum / (float)C;                    // post_var
        orow[EC + 3 * E + 4] = mixent + spl / (float)E;              // mutual_info
    }
}

extern "C" void kernel_launch(void* const* d_in, const int* in_sizes, int n_in,
                              void* d_out, int out_size)
{
    const float* p = (const float*)d_in[0];
    float* out = (float*)d_out;
    const int B = in_sizes[0] / EC;    // 8192 for this problem's shapes
    gating_feats_k1<<<2 * B, NT>>>(p, out);
    gating_feats_k2<<<(B * E + 255) / 256, 256>>>(out, B);
}

// round 16
// speedup vs baseline: 1.2463x; 1.0334x over previous
#include <cuda_runtime.h>
#include <cstdint>

// GatingFeatureExtractor: p[B, E=8, C=1000] fp32 -> feats[B, E*C + 3E + 5] fp32.
// Split-row design: 2 CTAs per row (128 threads, ~16KB smem each) so ~10-12
// independent CTAs/SM pipeline load/compute/store via the HW scheduler.
//   k1 (grid 2B): CTA x -> (b = x>>1, half = x&1), classes [500*half, +500):
//     A:   cp.async 16KB stage
//     B+D: warp w -> experts 2w,2w+1: top2/argmax partial AND the shifted
//          aligned output copy fused into the same float4 loop (one smem pass)
//     C:   thread t<125 owns 4 classes: plogp[8], prefix-KL cross, mixture
//          entropy, variance partials
//     partials -> __device__ scratch (AoS-by-x: 8-lane-coalesced k2 reads)
//   k2 (thread per (row, expert)): merge halves, write 3 per-expert cols;
//     8-lane shuffle reduce -> lane e==0 writes the 5 per-row scalars.

#define EPS_F 1e-8f

constexpr int E = 8;
constexpr int C = 1000;
constexpr int EC = E * C;                  // 8000
constexpr int OUTW = EC + 3 * E + 5;       // 8029
constexpr int HALF = 500;                  // classes per CTA
constexpr int H4 = HALF / 4;               // 125 float4 per expert-segment
constexpr int NT = 128;
constexpr int NW = NT / 32;                // 4
constexpr int BMAX = 8192;

// partial scratch, AoS by x = 2*b + half: lanes e=0..7 read consecutive floats
__device__ float g_red[2 * BMAX][16];      // [0..7]=plogp, 8=cross, 9=mixent, 10=var
__device__ float g_m1[2 * BMAX][E];
__device__ float g_m2[2 * BMAX][E];
__device__ int   g_i1[2 * BMAX][E];

__device__ __forceinline__ void cp_async16(uint32_t saddr, const void* gptr) {
    asm volatile("cp.async.cg.shared.global [%0], [%1], 16;\n" ::"r"(saddr), "l"(gptr));
}

__global__ __launch_bounds__(NT)
void gating_feats_k1(const float* __restrict__ pin, float* __restrict__ out)
{
    __shared__ __align__(16) float sp[E * HALF + 4];   // +4 pad: overlap read
    __shared__ float sh_red[NW][11];

    const int x    = blockIdx.x;
    const int b    = x >> 1;
    const int half = x & 1;
    const int tid  = threadIdx.x;
    const int wid  = tid >> 5;
    const int lane = tid & 31;

    const float* __restrict__ pr = pin + (size_t)b * EC + half * HALF; // + e*C
    float* __restrict__ orow = out + (size_t)b * OUTW;
    // (b*OUTW)%4 == b%4 since OUTW%4==1; every segment start has same h.
    const int h = (4 - (b & 3)) & 3;

    // ---------------- Phase A: stage 8 x 2000B segments via cp.async ----------
    if (tid < H4) {
        uint32_t sbase = (uint32_t)__cvta_generic_to_shared(sp) + 16u * (uint32_t)tid;
#pragma unroll
        for (int e = 0; e < E; e++)
            cp_async16(sbase + (uint32_t)(e * HALF * 4), pr + e * C + 4 * tid);
    }
    asm volatile("cp.async.commit_group;\n" ::: "memory");
    asm volatile("cp.async.wait_group 0;\n" ::: "memory");
    __syncthreads();

    // ---- Phase B+D: warp w -> experts 2w,2w+1: top2/argmax + fused copy ----
#pragma unroll
    for (int s = 0; s < 2; s++) {
        const int e = 2 * wid + s;
        const float* __restrict__ seg = sp + e * HALF;
        const float4* __restrict__ seg4 = reinterpret_cast<const float4*>(seg);
        float* __restrict__ dseg = orow + e * C + half * HALF;
        float m1 = -1.f, m2 = -1.f;
        int i1 = 0x7fffffff;
#pragma unroll
        for (int k = 0; k < 4; k++) {
            int idx = lane + 32 * k;
            if (idx < H4) {
                float4 v = seg4[idx];
                float vv[4] = {v.x, v.y, v.z, v.w};
#pragma unroll
                for (int i = 0; i < 4; i++) {
                    float f = vv[i];
                    if (f > m1) { m2 = m1; m1 = f; i1 = half * HALF + 4 * idx + i; }
                    else        { m2 = fmaxf(m2, f); }
                }
                // ---- fused shifted aligned store of this quad ----
                if (h == 0) {
                    reinterpret_cast<float4*>(dseg)[idx] = v;
                } else {
                    if (idx < H4 - 1) {
                        float4 w = seg4[idx + 1];       // smem-hot overlap read
                        float4 o;
                        if (h == 1)      { o.x = v.y; o.y = v.z; o.z = v.w; o.w = w.x; }
                        else if (h == 2) { o.x = v.z; o.y = v.w; o.z = w.x; o.w = w.y; }
                        else             { o.x = v.w; o.y = w.x; o.z = w.y; o.w = w.z; }
                        *reinterpret_cast<float4*>(dseg + h + 4 * idx) = o;
                    } else {
                        // tail: last (4-h) floats = vv[h..3] of quad 124
#pragma unroll
                        for (int i = 0; i < 4; i++)
                            if (i >= h) dseg[496 + i] = vv[i];
                    }
                    if (idx == 0)                        // head: first h floats
                        for (int i = 0; i < h; i++) dseg[i] = vv[i];
                }
            }
        }
#pragma unroll
        for (int off = 16; off; off >>= 1) {
            float o1 = __shfl_xor_sync(0xffffffffu, m1, off);
            float o2 = __shfl_xor_sync(0xffffffffu, m2, off);
            int   oi = __shfl_xor_sync(0xffffffffu, i1, off);
            if (o1 > m1 || (o1 == m1 && oi < i1)) {
                m2 = fmaxf(m1, o2); m1 = o1; i1 = oi;
            } else {
                m2 = fmaxf(m2, o1);
            }
        }
        if (lane == 0) { g_m1[x][e] = m1; g_m2[x][e] = m2; g_i1[x][e] = i1; }
    }

    // -------- Phase C: thread t<125 owns local classes 4t..4t+3 --------
    {
        float plogp[E];
#pragma unroll
        for (int e = 0; e < E; e++) plogp[e] = 0.f;
        float s_cross = 0.f, s_mixent = 0.f, s_var = 0.f;

        if (tid < H4) {
            float pre[4] = {0.f, 0.f, 0.f, 0.f};
            float ssq[4] = {0.f, 0.f, 0.f, 0.f};
#pragma unroll
            for (int e = 0; e < E; e++) {
                float4 v = reinterpret_cast<const float4*>(sp + e * HALF)[tid];
                float vv[4] = {v.x, v.y, v.z, v.w};
                float pe = 0.f;
#pragma unroll
                for (int i = 0; i < 4; i++) {
                    float f = vv[i];
                    float lg = __logf(f + EPS_F);
                    pe = fmaf(f, lg, pe);
                    s_cross = fmaf(lg, pre[i], s_cross);  // sum_{i<j} p_i * logp_j
                    pre[i] += f;
                    ssq[i] = fmaf(f, f, ssq[i]);
                }
                plogp[e] = pe;
            }
#pragma unroll
            for (int i = 0; i < 4; i++) {
                float m = pre[i] * (1.0f / E);      // full expert sum for this class
                s_mixent = fmaf(-m, __logf(m + EPS_F), s_mixent);
                s_var = fmaf(ssq[i] - (float)E * m * m, 1.0f / (float)(E - 1), s_var);
            }
        }
        float r[11];
#pragma unroll
        for (int e = 0; e < E; e++) r[e] = plogp[e];
        r[8] = s_cross; r[9] = s_mixent; r[10] = s_var;
#pragma unroll
        for (int off = 16; off; off >>= 1)
#pragma unroll
            for (int k = 0; k < 11; k++)
                r[k] += __shfl_xor_sync(0xffffffffu, r[k], off);
        if (lane == 0)
#pragma unroll
            for (int k = 0; k < 11; k++) sh_red[wid][k] = r[k];
    }
    __syncthreads();
    if (tid == 0) {
#pragma unroll
        for (int k = 0; k < 11; k++)
            g_red[x][k] = sh_red[0][k] + sh_red[1][k] + sh_red[2][k] + sh_red[3][k];
    }
}

// ---- combine: thread (b, e) merges expert e of row b (coalesced AoS reads);
//      lane e==0 of each 8-lane group writes the 5 per-row scalars. ----
__global__ __launch_bounds__(256)
void gating_feats_k2(float* __restrict__ out, int B)
{
    const int g = blockIdx.x * blockDim.x + threadIdx.x;   // B*8 threads
    const int b = g >> 3;
    const int e = g & 7;
    if (b >= B) return;
    float* __restrict__ orow = out + (size_t)b * OUTW;
    const int p0 = 2 * b, p1 = 2 * b + 1;

    // 8-lane groups read consecutive floats -> one 32B sector per load
    float m1 = g_m1[p0][e], m2 = g_m2[p0][e];
    int   i1 = g_i1[p0][e];
    {
        float o1 = g_m1[p1][e], o2 = g_m2[p1][e];
        int   oi = g_i1[p1][e];
        if (o1 > m1 || (o1 == m1 && oi < i1)) {
            m2 = fmaxf(m1, o2); m1 = o1; i1 = oi;
        } else {
            m2 = fmaxf(m2, o1);
        }
    }
    const float pl = g_red[p0][e] + g_red[p1][e];

    orow[EC + e]         = -pl;          // expert_entropy
    orow[EC + E + e]     = m1;           // expert_confidence
    orow[EC + 2 * E + e] = m1 - m2;      // expert_margin

    // 8-lane group reductions (groups are lane-aligned: blockDim % 8 == 0)
    float spl = pl, wsum = pl * (float)(E - 1 - e);
#pragma unroll
    for (int off = 4; off; off >>= 1) {
        spl  += __shfl_xor_sync(0xffffffffu, spl, off);
        wsum += __shfl_xor_sync(0xffffffffu, wsum, off);
    }
    // gather the 8 argmax indices of this row to every lane
    const int lane = threadIdx.x & 31;
    const int base = lane & ~7;
    int args[E];
#pragma unroll
    for (int j = 0; j < E; j++)
        args[j] = __shfl_sync(0xffffffffu, i1, base + j);

    if (e == 0) {
        // sort 8 argmax indices, count unique
        for (int i = 1; i < E; i++) {
            int key = args[i]; int j = i - 1;
            while (j >= 0 && args[j] > key) { args[j + 1] = args[j]; j--; }
            args[j + 1] = key;
        }
        int nuniq = 1;
        for (int i = 1; i < E; i++) nuniq += (args[i] != args[i - 1]) ? 1 : 0;

        const float Sx     = g_red[p0][8]  + g_red[p1][8];
        const float mixent = g_red[p0][9]  + g_red[p1][9];
        const float varsum = g_red[p0][10] + g_red[p1][10];
        const int n_pairs = E * (E - 1) / 2;

        orow[EC + 3 * E + 0] = (float)(nuniq - 1) / (float)(E - 1);  // disagreement
        orow[EC + 3 * E + 1] = (wsum - Sx) / (float)n_pairs;         // mean_pairwise_kl
        orow[EC + 3 * E + 2] = mixent;                               // mixture_entropy
        orow[EC + 3 * E + 3] = varsum / (float)C;                    // post_var
        orow[EC + 3 * E + 4] = mixent + spl / (float)E;              // mutual_info
    }
}

extern "C" void kernel_launch(void* const* d_in, const int* in_sizes, int n_in,
                              void* d_out, int out_size)
{
    const float* p = (const float*)d_in[0];
    float* out = (float*)d_out;
    const int B = in_sizes[0] / EC;    // 8192 for this problem's shapes
    gating_feats_k1<<<2 * B, NT>>>(p, out);
    gating_feats_k2<<<(B * E + 255) / 256, 256>>>(out, B);
}

// round 17
// speedup vs baseline: 1.2553x; 1.0072x over previous
#include <cuda_runtime.h>
#include <cstdint>

// GatingFeatureExtractor: p[B, E=8, C=1000] fp32 -> feats[B, E*C + 3E + 5] fp32.
// Split-row design: 2 CTAs per row (128 threads, ~16KB smem each) so ~10-12
// independent CTAs/SM pipeline load/compute/store via the HW scheduler.
//   k1 (grid 2B): CTA x -> (b = x>>1, half = x&1), classes [500*half, +500):
//     A:   cp.async 16KB stage
//     B+D: warp w -> experts 2w,2w+1: top2/argmax partial AND the shifted
//          aligned output copy fused into the same float4 loop (one smem pass)
//     C:   thread t<125 owns 4 classes: plogp[8], prefix-KL cross, mixture
//          entropy, variance partials
//     post: packed float4 scratch records (one LDG.128 per record in k2)
//   k2 (thread per (row, expert)): 2x LDG.128 merge, write 3 per-expert cols;
//     8-lane shuffle reduce -> lane e==0 writes the 5 per-row scalars.

#define EPS_F 1e-8f

constexpr int E = 8;
constexpr int C = 1000;
constexpr int EC = E * C;                  // 8000
constexpr int OUTW = EC + 3 * E + 5;       // 8029
constexpr int HALF = 500;                  // classes per CTA
constexpr int H4 = HALF / 4;               // 125 float4 per expert-segment
constexpr int NT = 128;
constexpr int NW = NT / 32;                // 4
constexpr int BMAX = 8192;

// packed partial scratch, x = 2*b + half:
//   g_pk[x][e] = {plogp, m1, m2, i1_bits};  g_sc[x] = {cross, mixent, var, 0}
__device__ float4 g_pk[2 * BMAX][E];
__device__ float4 g_sc[2 * BMAX];

__device__ __forceinline__ void cp_async16(uint32_t saddr, const void* gptr) {
    asm volatile("cp.async.cg.shared.global [%0], [%1], 16;\n" ::"r"(saddr), "l"(gptr));
}

__global__ __launch_bounds__(NT)
void gating_feats_k1(const float* __restrict__ pin, float* __restrict__ out)
{
    __shared__ __align__(16) float sp[E * HALF + 4];   // +4 pad: overlap read
    __shared__ float sh_red[NW][11];
    __shared__ float sh_m1[E], sh_m2[E];
    __shared__ int   sh_i1[E];

    const int x    = blockIdx.x;
    const int b    = x >> 1;
    const int half = x & 1;
    const int tid  = threadIdx.x;
    const int wid  = tid >> 5;
    const int lane = tid & 31;

    const float* __restrict__ pr = pin + (size_t)b * EC + half * HALF; // + e*C
    float* __restrict__ orow = out + (size_t)b * OUTW;
    // (b*OUTW)%4 == b%4 since OUTW%4==1; every segment start has same h.
    const int h = (4 - (b & 3)) & 3;

    // ---------------- Phase A: stage 8 x 2000B segments via cp.async ----------
    if (tid < H4) {
        uint32_t sbase = (uint32_t)__cvta_generic_to_shared(sp) + 16u * (uint32_t)tid;
#pragma unroll
        for (int e = 0; e < E; e++)
            cp_async16(sbase + (uint32_t)(e * HALF * 4), pr + e * C + 4 * tid);
    }
    asm volatile("cp.async.commit_group;\n" ::: "memory");
    asm volatile("cp.async.wait_group 0;\n" ::: "memory");
    __syncthreads();

    // ---- Phase B+D: warp w -> experts 2w,2w+1: top2/argmax + fused copy ----
#pragma unroll
    for (int s = 0; s < 2; s++) {
        const int e = 2 * wid + s;
        const float* __restrict__ seg = sp + e * HALF;
        const float4* __restrict__ seg4 = reinterpret_cast<const float4*>(seg);
        float* __restrict__ dseg = orow + e * C + half * HALF;
        float m1 = -1.f, m2 = -1.f;
        int i1 = 0x7fffffff;
#pragma unroll
        for (int k = 0; k < 4; k++) {
            int idx = lane + 32 * k;
            if (idx < H4) {
                float4 v = seg4[idx];
                float vv[4] = {v.x, v.y, v.z, v.w};
#pragma unroll
                for (int i = 0; i < 4; i++) {
                    float f = vv[i];
                    if (f > m1) { m2 = m1; m1 = f; i1 = half * HALF + 4 * idx + i; }
                    else        { m2 = fmaxf(m2, f); }
                }
                // ---- fused shifted aligned store of this quad ----
                if (h == 0) {
                    reinterpret_cast<float4*>(dseg)[idx] = v;
                } else {
                    if (idx < H4 - 1) {
                        float4 w = seg4[idx + 1];       // smem-hot overlap read
                        float4 o;
                        if (h == 1)      { o.x = v.y; o.y = v.z; o.z = v.w; o.w = w.x; }
                        else if (h == 2) { o.x = v.z; o.y = v.w; o.z = w.x; o.w = w.y; }
                        else             { o.x = v.w; o.y = w.x; o.z = w.y; o.w = w.z; }
                        *reinterpret_cast<float4*>(dseg + h + 4 * idx) = o;
                    } else {
                        // tail: last (4-h) floats = vv[h..3] of quad 124
#pragma unroll
                        for (int i = 0; i < 4; i++)
                            if (i >= h) dseg[496 + i] = vv[i];
                    }
                    if (idx == 0)                        // head: first h floats
                        for (int i = 0; i < h; i++) dseg[i] = vv[i];
                }
            }
        }
#pragma unroll
        for (int off = 16; off; off >>= 1) {
            float o1 = __shfl_xor_sync(0xffffffffu, m1, off);
            float o2 = __shfl_xor_sync(0xffffffffu, m2, off);
            int   oi = __shfl_xor_sync(0xffffffffu, i1, off);
            if (o1 > m1 || (o1 == m1 && oi < i1)) {
                m2 = fmaxf(m1, o2); m1 = o1; i1 = oi;
            } else {
                m2 = fmaxf(m2, o1);
            }
        }
        if (lane == 0) { sh_m1[e] = m1; sh_m2[e] = m2; sh_i1[e] = i1; }
    }

    // -------- Phase C: thread t<125 owns local classes 4t..4t+3 --------
    {
        float plogp[E];
#pragma unroll
        for (int e = 0; e < E; e++) plogp[e] = 0.f;
        float s_cross = 0.f, s_mixent = 0.f, s_var = 0.f;

        if (tid < H4) {
            float pre[4] = {0.f, 0.f, 0.f, 0.f};
            float ssq[4] = {0.f, 0.f, 0.f, 0.f};
#pragma unroll
            for (int e = 0; e < E; e++) {
                float4 v = reinterpret_cast<const float4*>(sp + e * HALF)[tid];
                float vv[4] = {v.x, v.y, v.z, v.w};
                float pe = 0.f;
#pragma unroll
                for (int i = 0; i < 4; i++) {
                    float f = vv[i];
                    float lg = __logf(f + EPS_F);
                    pe = fmaf(f, lg, pe);
                    s_cross = fmaf(lg, pre[i], s_cross);  // sum_{i<j} p_i * logp_j
                    pre[i] += f;
                    ssq[i] = fmaf(f, f, ssq[i]);
                }
                plogp[e] = pe;
            }
#pragma unroll
            for (int i = 0; i < 4; i++) {
                float m = pre[i] * (1.0f / E);      // full expert sum for this class
                s_mixent = fmaf(-m, __logf(m + EPS_F), s_mixent);
                s_var = fmaf(ssq[i] - (float)E * m * m, 1.0f / (float)(E - 1), s_var);
            }
        }
        float r[11];
#pragma unroll
        for (int e = 0; e < E; e++) r[e] = plogp[e];
        r[8] = s_cross; r[9] = s_mixent; r[10] = s_var;
#pragma unroll
        for (int off = 16; off; off >>= 1)
#pragma unroll
            for (int k = 0; k < 11; k++)
                r[k] += __shfl_xor_sync(0xffffffffu, r[k], off);
        if (lane == 0)
#pragma unroll
            for (int k = 0; k < 11; k++) sh_red[wid][k] = r[k];
    }
    __syncthreads();

    // -------- post packed records: tid<8 -> g_pk[x][tid], tid==8 -> g_sc[x] ----
    if (tid < E) {
        const int e = tid;
        float pl = sh_red[0][e] + sh_red[1][e] + sh_red[2][e] + sh_red[3][e];
        float4 rec;
        rec.x = pl;
        rec.y = sh_m1[e];
        rec.z = sh_m2[e];
        rec.w = __int_as_float(sh_i1[e]);
        g_pk[x][e] = rec;                              // 8 lanes: 128B coalesced
    } else if (tid == E) {
        float4 sc;
        sc.x = sh_red[0][8]  + sh_red[1][8]  + sh_red[2][8]  + sh_red[3][8];
        sc.y = sh_red[0][9]  + sh_red[1][9]  + sh_red[2][9]  + sh_red[3][9];
        sc.z = sh_red[0][10] + sh_red[1][10] + sh_red[2][10] + sh_red[3][10];
        sc.w = 0.f;
        g_sc[x] = sc;
    }
}

// ---- combine: thread (b, e): two LDG.128 merge; lane e==0 of each 8-lane
//      group writes the 5 per-row scalars. ----
__global__ __launch_bounds__(256)
void gating_feats_k2(float* __restrict__ out, int B)
{
    const int g = blockIdx.x * blockDim.x + threadIdx.x;   // B*8 threads
    const int b = g >> 3;
    const int e = g & 7;
    if (b >= B) return;
    float* __restrict__ orow = out + (size_t)b * OUTW;
    const int p0 = 2 * b, p1 = 2 * b + 1;

    const float4 a0 = g_pk[p0][e];     // lanes e=0..7: 128B coalesced
    const float4 a1 = g_pk[p1][e];

    float m1 = a0.y, m2 = a0.z;
    int   i1 = __float_as_int(a0.w);
    {
        float o1 = a1.y, o2 = a1.z;
        int   oi = __float_as_int(a1.w);
        if (o1 > m1 || (o1 == m1 && oi < i1)) {
            m2 = fmaxf(m1, o2); m1 = o1; i1 = oi;
        } else {
            m2 = fmaxf(m2, o1);
        }
    }
    const float pl = a0.x + a1.x;

    orow[EC + e]         = -pl;          // expert_entropy
    orow[EC + E + e]     = m1;           // expert_confidence
    orow[EC + 2 * E + e] = m1 - m2;      // expert_margin

    // 8-lane group reductions (groups are lane-aligned: blockDim % 8 == 0)
    float spl = pl, wsum = pl * (float)(E - 1 - e);
#pragma unroll
    for (int off = 4; off; off >>= 1) {
        spl  += __shfl_xor_sync(0xffffffffu, spl, off);
        wsum += __shfl_xor_sync(0xffffffffu, wsum, off);
    }
    // gather the 8 argmax indices of this row to every lane
    const int lane = threadIdx.x & 31;
    const int base = lane & ~7;
    int args[E];
#pragma unroll
    for (int j = 0; j < E; j++)
        args[j] = __shfl_sync(0xffffffffu, i1, base + j);

    if (e == 0) {
        // sort 8 argmax indices, count unique
        for (int i = 1; i < E; i++) {
            int key = args[i]; int j = i - 1;
            while (j >= 0 && args[j] > key) { args[j + 1] = args[j]; j--; }
            args[j + 1] = key;
        }
        int nuniq = 1;
        for (int i = 1; i < E; i++) nuniq += (args[i] != args[i - 1]) ? 1 : 0;

        const float4 s0 = g_sc[p0];
        const float4 s1 = g_sc[p1];
        const float Sx     = s0.x + s1.x;
        const float mixent = s0.y + s1.y;
        const float varsum = s0.z + s1.z;
        const int n_pairs = E * (E - 1) / 2;

        orow[EC + 3 * E + 0] = (float)(nuniq - 1) / (float)(E - 1);  // disagreement
        orow[EC + 3 * E + 1] = (wsum - Sx) / (float)n_pairs;         // mean_pairwise_kl
        orow[EC + 3 * E + 2] = mixent;                               // mixture_entropy
        orow[EC + 3 * E + 3] = varsum / (float)C;                    // post_var
        orow[EC + 3 * E + 4] = mixent + spl / (float)E;              // mutual_info
    }
}

extern "C" void kernel_launch(void* const* d_in, const int* in_sizes, int n_in,
                              void* d_out, int out_size)
{
    const float* p = (const float*)d_in[0];
    float* out = (float*)d_out;
    const int B = in_sizes[0] / EC;    // 8192 for this problem's shapes
    gating_feats_k1<<<2 * B, NT>>>(p, out);
    gating_feats_k2<<<(B * E + 255) / 256, 256>>>(out, B);
}